// round 8
// baseline (speedup 1.0000x reference)
#include <cuda_runtime.h>
#include <cstdint>
#include <cstddef>

// ---------------------------------------------------------------------------
// W8A8 Linear. Evidence from R4/R6 (two different fragment-load schemes ->
// bit-identical rel_err) says the GEMM machinery is consistent and the input
// BYTES were misinterpreted: the harness widens int8 inputs (dtype list has
// no int8). This version detects the input encoding on-device and converts
// to packed int8 scratch, then runs the verified IMMA pipeline.
//
//   out[m,n] = alpha * sum_k x[m,k]*w[n,k] + bias[n]
//   x [M=8192, K=4096], w [N=4096, K=4096] ([out,in] == B[N,K]),
//   bias fp32 [4096], alpha fp32 scalar, out fp32 [M,N].
//
// GEMM: mma.sync.m16n8k32.s8, CTA tile 128x128, K chunk 128B, 4-stage
// cp.async pipeline, 8 warps, warp tile 64x32, explicit swizzled LDS frags.
// ---------------------------------------------------------------------------

static constexpr int K_TOTAL = 4096;
static constexpr int N_TOTAL = 4096;
static constexpr int M_MAX   = 8192;
static constexpr int BM = 128;
static constexpr int BN = 128;
static constexpr int BK = 128;                 // bytes per K chunk
static constexpr int STAGES = 4;
static constexpr int K_CHUNKS = K_TOTAL / BK;  // 32

static constexpr int A_BYTES = BM * BK;                    // 16384
static constexpr int B_BYTES = BN * BK;                    // 16384
static constexpr int STAGE_BYTES = A_BYTES + B_BYTES;      // 32768
static constexpr int SMEM_TOTAL = STAGES * STAGE_BYTES;    // 131072

static constexpr int NUM_THREADS = 256;

// ---------------------------------------------------------------------------
// Scratch (static device globals — no allocation)
// ---------------------------------------------------------------------------
__device__ int8_t g_x8[(size_t)M_MAX * K_TOTAL];     // 32 MB
__device__ int8_t g_w8[(size_t)N_TOTAL * K_TOTAL];   // 16 MB
__device__ int    g_wide;                            // 1 = 4-byte elements

// ---------------------------------------------------------------------------
// Input conversion
// ---------------------------------------------------------------------------

// One element stored in a 32-bit word: either an int32 in [-127,127] or the
// bit pattern of a float32 holding a small integer. Handles both per-element.
__device__ __forceinline__ int fix_elem(int v) {
    if ((unsigned)(v + 127) <= 254u) return v;              // int32 encoding
    return __float2int_rn(__int_as_float(v));               // float32 encoding
}

__global__ void detect_kernel(const int* __restrict__ probe) {
    if (threadIdx.x == 0) {
        int good = 0;
        for (int i = 0; i < 1024; i++) {
            const int v = probe[i];
            const float f = __int_as_float(v);
            const bool small_int = (unsigned)(v + 127) <= 254u;
            const bool small_flt = (f >= -127.5f && f <= 127.5f);
            if (small_int || small_flt) good++;
        }
        g_wide = (good >= 512) ? 1 : 0;
    }
}

// Each thread produces 16 packed int8 output bytes.
__global__ void cvt_kernel(const void* __restrict__ src, int sel, int n16) {
    const int i = blockIdx.x * blockDim.x + threadIdx.x;
    if (i >= n16) return;
    int8_t* dst = sel ? g_w8 : g_x8;
    if (g_wide) {
        const int4* s = reinterpret_cast<const int4*>(src) + (size_t)i * 4;
        uint32_t p[4];
        #pragma unroll
        for (int j = 0; j < 4; j++) {
            const int4 v = s[j];
            p[j] =  ((uint32_t)fix_elem(v.x) & 0xFFu)
                 | (((uint32_t)fix_elem(v.y) & 0xFFu) << 8)
                 | (((uint32_t)fix_elem(v.z) & 0xFFu) << 16)
                 | (((uint32_t)fix_elem(v.w) & 0xFFu) << 24);
        }
        reinterpret_cast<uint4*>(dst)[i] = make_uint4(p[0], p[1], p[2], p[3]);
    } else {
        reinterpret_cast<int4*>(dst)[i] =
            reinterpret_cast<const int4*>(src)[i];
    }
}

// ---------------------------------------------------------------------------
// PTX helpers (baseline PTX only — 'a'-gated instructions unavailable)
// ---------------------------------------------------------------------------

__device__ __forceinline__ uint32_t smem_u32(const void* p) {
    uint32_t a;
    asm("{ .reg .u64 t; cvta.to.shared.u64 t, %1; cvt.u32.u64 %0, t; }"
        : "=r"(a) : "l"(p));
    return a;
}

__device__ __forceinline__ void cp16(uint32_t dst_smem, const void* src_gmem) {
    asm volatile("cp.async.cg.shared.global [%0], [%1], 16;"
                 :: "r"(dst_smem), "l"(src_gmem));
}

__device__ __forceinline__ void cp_commit() {
    asm volatile("cp.async.commit_group;" ::: "memory");
}

template <int N>
__device__ __forceinline__ void cp_wait() {
    asm volatile("cp.async.wait_group %0;" :: "n"(N) : "memory");
}

__device__ __forceinline__ void imma16832(int* d, const uint32_t* a,
                                          const uint32_t* b) {
    asm volatile(
        "mma.sync.aligned.m16n8k32.row.col.s32.s8.s8.s32 "
        "{%0,%1,%2,%3}, {%4,%5,%6,%7}, {%8,%9}, {%0,%1,%2,%3};"
        : "+r"(d[0]), "+r"(d[1]), "+r"(d[2]), "+r"(d[3])
        : "r"(a[0]), "r"(a[1]), "r"(a[2]), "r"(a[3]), "r"(b[0]), "r"(b[1]));
}

// ---------------------------------------------------------------------------
// GEMM kernel (verified-consistent machinery from R6, reading int8 scratch)
// ---------------------------------------------------------------------------

__global__ void __launch_bounds__(NUM_THREADS, 1)
w8a8_imma_kernel(float* __restrict__ out,
                 const float* __restrict__ bias,
                 const float* __restrict__ alpha_p)
{
    extern __shared__ char smem[];
    const uint32_t sb = smem_u32(smem);
    const int tid = threadIdx.x;
    const int wid = tid >> 5;
    const int lid = tid & 31;

    const int m_base = blockIdx.y * BM;
    const int n_base = blockIdx.x * BN;

    const int warp_m = wid & 1;    // 0..1 -> 64-row slab
    const int warp_n = wid >> 1;   // 0..3 -> 32-col slab

    // ---- producer precompute: 4 A units + 4 B units of 16B per thread -----
    // store swizzle: (row r, 16B col c) -> r*BK + (c ^ ((r&7)<<4))
    uint32_t dst_off[4];
    const int8_t* a_src[4];
    const int8_t* b_src[4];
    #pragma unroll
    for (int i = 0; i < 4; i++) {
        const int u = tid + i * 256;           // 0..1023 units
        const int r = u >> 3;                  // tile row 0..127
        const int c = (u & 7) * 16;            // byte col 0..112
        dst_off[i] = (uint32_t)(r * BK + (c ^ ((r & 7) << 4)));
        a_src[i] = g_x8 + (size_t)(m_base + r) * K_TOTAL + c;
        b_src[i] = g_w8 + (size_t)(n_base + r) * K_TOTAL + c;
    }

    // ---- consumer precompute ----------------------------------------------
    // mma m16n8k32 s8 fragments (g = lid>>2, tg = lid&3):
    //   A: a0=(row g, k 4tg..+3) a1=(row g+8, same) a2=(g, +16) a3=(g+8, +16)
    //   B: b0=(n g, k 4tg..+3)   b1=(n g, +16)
    //   C: c0=(g,2tg) c1=(g,2tg+1) c2=(g+8,2tg) c3=(g+8,2tg+1)
    const int g  = lid >> 2;
    const int tg = lid & 3;
    const uint32_t maskg = (uint32_t)(g << 4);
    const uint32_t kbase = (uint32_t)(4 * tg);
    const uint32_t a_row_off = (uint32_t)((warp_m * 64 + g) * BK);
    const uint32_t b_row_off = (uint32_t)((warp_n * 32 + g) * BK);

    int acc[4][4][4];
    #pragma unroll
    for (int fm = 0; fm < 4; fm++)
        #pragma unroll
        for (int fn = 0; fn < 4; fn++)
            #pragma unroll
            for (int q = 0; q < 4; q++) acc[fm][fn][q] = 0;

    // ---- prologue: fill stages 0..2 ---------------------------------------
    #pragma unroll
    for (int s = 0; s < STAGES - 1; s++) {
        const uint32_t sA = sb + s * STAGE_BYTES;
        const uint32_t sB = sA + A_BYTES;
        #pragma unroll
        for (int i = 0; i < 4; i++) cp16(sA + dst_off[i], a_src[i] + s * BK);
        #pragma unroll
        for (int i = 0; i < 4; i++) cp16(sB + dst_off[i], b_src[i] + s * BK);
        cp_commit();
    }

    // ---- main loop --------------------------------------------------------
    #pragma unroll 1
    for (int kc = 0; kc < K_CHUNKS; kc++) {
        cp_wait<STAGES - 2>();
        __syncthreads();

        const int kn = kc + STAGES - 1;
        if (kn < K_CHUNKS) {
            const int s = kn & (STAGES - 1);
            const uint32_t sA = sb + s * STAGE_BYTES;
            const uint32_t sB = sA + A_BYTES;
            #pragma unroll
            for (int i = 0; i < 4; i++) cp16(sA + dst_off[i], a_src[i] + kn * BK);
            #pragma unroll
            for (int i = 0; i < 4; i++) cp16(sB + dst_off[i], b_src[i] + kn * BK);
        }
        cp_commit();

        const char* sAp = smem + (kc & (STAGES - 1)) * STAGE_BYTES;
        const char* sBp = sAp + A_BYTES;

        #pragma unroll
        for (int ks = 0; ks < 4; ks++) {
            const uint32_t c0 = ((uint32_t)(ks << 5) + kbase) ^ maskg;
            const uint32_t c1 = c0 ^ 16u;

            uint32_t a[4][4];
            #pragma unroll
            for (int fm = 0; fm < 4; fm++) {
                const char* base = sAp + a_row_off + fm * (16 * BK);
                a[fm][0] = *reinterpret_cast<const uint32_t*>(base + c0);
                a[fm][1] = *reinterpret_cast<const uint32_t*>(base + 8 * BK + c0);
                a[fm][2] = *reinterpret_cast<const uint32_t*>(base + c1);
                a[fm][3] = *reinterpret_cast<const uint32_t*>(base + 8 * BK + c1);
            }
            uint32_t bf[4][2];
            #pragma unroll
            for (int fn = 0; fn < 4; fn++) {
                const char* base = sBp + b_row_off + fn * (8 * BK);
                bf[fn][0] = *reinterpret_cast<const uint32_t*>(base + c0);
                bf[fn][1] = *reinterpret_cast<const uint32_t*>(base + c1);
            }
            #pragma unroll
            for (int fm = 0; fm < 4; fm++)
                #pragma unroll
                for (int fn = 0; fn < 4; fn++)
                    imma16832(acc[fm][fn], a[fm], bf[fn]);
        }
    }
    cp_wait<0>();

    // ---- epilogue: alpha * acc + bias -------------------------------------
    const float alpha = __ldg(alpha_p);

    #pragma unroll
    for (int fm = 0; fm < 4; fm++) {
        const int row = m_base + warp_m * 64 + fm * 16 + g;
        float* o0 = out + (size_t)row * N_TOTAL;
        float* o1 = out + (size_t)(row + 8) * N_TOTAL;
        #pragma unroll
        for (int fn = 0; fn < 4; fn++) {
            const int col = n_base + warp_n * 32 + fn * 8 + tg * 2;
            const float b0 = __ldg(bias + col);
            const float b1 = __ldg(bias + col + 1);
            float2 v0, v1;
            v0.x = fmaf(alpha, (float)acc[fm][fn][0], b0);
            v0.y = fmaf(alpha, (float)acc[fm][fn][1], b1);
            v1.x = fmaf(alpha, (float)acc[fm][fn][2], b0);
            v1.y = fmaf(alpha, (float)acc[fm][fn][3], b1);
            *reinterpret_cast<float2*>(o0 + col) = v0;
            *reinterpret_cast<float2*>(o1 + col) = v1;
        }
    }
}

// ---------------------------------------------------------------------------
// Launch — inputs identified by element count; M from out_size.
// Sequence: detect -> convert x -> convert w -> GEMM (stream-ordered).
// ---------------------------------------------------------------------------

extern "C" void kernel_launch(void* const* d_in, const int* in_sizes, int n_in,
                              void* d_out, int out_size)
{
    const void* px = nullptr;
    const void* pw = nullptr;
    const void* pb = nullptr;
    const void* pa = nullptr;

    for (int i = 0; i < n_in; i++) {
        const long s = (long)in_sizes[i];
        if (s == 1)                            pa = d_in[i];
        else if (s == (long)N_TOTAL)           pb = d_in[i];
        else if (s == (long)N_TOTAL * K_TOTAL) pw = d_in[i];
        else                                   px = d_in[i];
    }
    if (!px || !pw || !pb || !pa) {   // fallback: declared order
        px = d_in[0]; pw = d_in[1]; pb = d_in[2]; pa = d_in[3];
    }

    const int M = out_size / N_TOTAL;           // 8192
    const int nx16 = (M * K_TOTAL) / 16;        // 2,097,152
    const int nw16 = (N_TOTAL * K_TOTAL) / 16;  // 1,048,576

    detect_kernel<<<1, 32>>>((const int*)px);
    cvt_kernel<<<(nx16 + 255) / 256, 256>>>(px, 0, nx16);
    cvt_kernel<<<(nw16 + 255) / 256, 256>>>(pw, 1, nw16);

    cudaFuncSetAttribute(w8a8_imma_kernel,
                         cudaFuncAttributeMaxDynamicSharedMemorySize, SMEM_TOTAL);

    dim3 grid(N_TOTAL / BN, M / BM);   // (32, 64)
    w8a8_imma_kernel<<<grid, NUM_THREADS, SMEM_TOTAL>>>(
        (float*)d_out, (const float*)pb, (const float*)pa);
}

// round 10
// speedup vs baseline: 2.2745x; 2.2745x over previous
#include <cuda_runtime.h>
#include <cuda_bf16.h>
#include <cstdint>
#include <cstddef>

// ---------------------------------------------------------------------------
// W8A8 Linear via legacy bf16 HMMA (mma.sync.m16n8k16.f32.bf16.bf16.f32).
//
// R8 evidence: int8 mma.sync saturates the legacy tensor pipe at only
// ~580 MACs/cyc/SM on sm_103 (tensor=91.2% @ 1971us). The legacy bf16 path
// is the compatibility path and likely runs at a much higher rate. Math is
// EXACT: int8 values are exact in bf16, products exact in fp32 accum, and
// integer partial sums stay far below 2^24.
//
//   out[m,n] = alpha * sum_k x[m,k]*w[n,k] + bias[n]
//
// Inputs arrive widened to 4-byte elements (R6->R8 finding); cvt kernels
// detect encoding and emit packed bf16 scratch. GEMM: CTA tile 128x128,
// K chunk 64 elems (128B rows — same swizzle algebra as the int8 version,
// byte-for-byte), 4-stage cp.async pipeline, 8 warps, warp tile 64x32.
// ---------------------------------------------------------------------------

static constexpr int K_TOTAL = 4096;
static constexpr int N_TOTAL = 4096;
static constexpr int M_MAX   = 8192;
static constexpr int BM = 128;
static constexpr int BN = 128;
static constexpr int BK_ELEM = 64;                   // bf16 elems per chunk
static constexpr int BKB = 128;                      // bytes per row per chunk
static constexpr int STAGES = 4;
static constexpr int K_CHUNKS = K_TOTAL / BK_ELEM;   // 64

static constexpr int A_BYTES = BM * BKB;                   // 16384
static constexpr int B_BYTES = BN * BKB;                   // 16384
static constexpr int STAGE_BYTES = A_BYTES + B_BYTES;      // 32768
static constexpr int SMEM_TOTAL = STAGES * STAGE_BYTES;    // 131072

static constexpr int NUM_THREADS = 256;

// ---------------------------------------------------------------------------
// Scratch (static device globals — no allocation)
// ---------------------------------------------------------------------------
__device__ __nv_bfloat16 g_xh[(size_t)M_MAX * K_TOTAL];    // 64 MB
__device__ __nv_bfloat16 g_wh[(size_t)N_TOTAL * K_TOTAL];  // 32 MB
__device__ int g_wide;                                     // 1 = 4B elements

// ---------------------------------------------------------------------------
// Input conversion
// ---------------------------------------------------------------------------

// One 32-bit word holding one logical int8 element: either an int32 in
// [-127,127] or the bit pattern of a float32 holding a small integer.
__device__ __forceinline__ float fix_elem(int v) {
    if ((unsigned)(v + 127) <= 254u) return (float)v;      // int32 encoding
    return __int_as_float(v);                              // float32 encoding
}

__global__ void detect_kernel(const int* __restrict__ probe) {
    if (threadIdx.x == 0) {
        int good = 0;
        for (int i = 0; i < 1024; i++) {
            const int v = probe[i];
            const float f = __int_as_float(v);
            const bool small_int = (unsigned)(v + 127) <= 254u;
            const bool small_flt = (f >= -127.5f && f <= 127.5f);
            if (small_int || small_flt) good++;
        }
        g_wide = (good >= 512) ? 1 : 0;
    }
}

// Each thread emits 8 bf16 (16B). Wide: reads 8x4B. Narrow: reads 8x1B int8.
__global__ void cvt_bf16_kernel(const void* __restrict__ src, int sel, int n8) {
    const int i = blockIdx.x * blockDim.x + threadIdx.x;
    if (i >= n8) return;
    __nv_bfloat16* dst = sel ? g_wh : g_xh;
    float v[8];
    if (g_wide) {
        const int4* s = reinterpret_cast<const int4*>(src) + (size_t)i * 2;
        const int4 w0 = s[0];
        const int4 w1 = s[1];
        v[0] = fix_elem(w0.x); v[1] = fix_elem(w0.y);
        v[2] = fix_elem(w0.z); v[3] = fix_elem(w0.w);
        v[4] = fix_elem(w1.x); v[5] = fix_elem(w1.y);
        v[6] = fix_elem(w1.z); v[7] = fix_elem(w1.w);
    } else {
        const uint2 p = reinterpret_cast<const uint2*>(src)[i];
        #pragma unroll
        for (int j = 0; j < 4; j++)
            v[j] = (float)(int8_t)((p.x >> (8 * j)) & 0xFFu);
        #pragma unroll
        for (int j = 0; j < 4; j++)
            v[4 + j] = (float)(int8_t)((p.y >> (8 * j)) & 0xFFu);
    }
    uint4 o;
    uint16_t h[8];
    #pragma unroll
    for (int j = 0; j < 8; j++) {
        const __nv_bfloat16 b = __float2bfloat16_rn(v[j]);
        h[j] = *reinterpret_cast<const uint16_t*>(&b);
    }
    o.x = (uint32_t)h[0] | ((uint32_t)h[1] << 16);
    o.y = (uint32_t)h[2] | ((uint32_t)h[3] << 16);
    o.z = (uint32_t)h[4] | ((uint32_t)h[5] << 16);
    o.w = (uint32_t)h[6] | ((uint32_t)h[7] << 16);
    reinterpret_cast<uint4*>(dst)[i] = o;
}

// ---------------------------------------------------------------------------
// PTX helpers (baseline PTX only)
// ---------------------------------------------------------------------------

__device__ __forceinline__ uint32_t smem_u32(const void* p) {
    uint32_t a;
    asm("{ .reg .u64 t; cvta.to.shared.u64 t, %1; cvt.u32.u64 %0, t; }"
        : "=r"(a) : "l"(p));
    return a;
}

__device__ __forceinline__ void cp16(uint32_t dst_smem, const void* src_gmem) {
    asm volatile("cp.async.cg.shared.global [%0], [%1], 16;"
                 :: "r"(dst_smem), "l"(src_gmem));
}

__device__ __forceinline__ void cp_commit() {
    asm volatile("cp.async.commit_group;" ::: "memory");
}

template <int N>
__device__ __forceinline__ void cp_wait() {
    asm volatile("cp.async.wait_group %0;" :: "n"(N) : "memory");
}

__device__ __forceinline__ void hmma16816(float* d, const uint32_t* a,
                                          const uint32_t* b) {
    asm volatile(
        "mma.sync.aligned.m16n8k16.row.col.f32.bf16.bf16.f32 "
        "{%0,%1,%2,%3}, {%4,%5,%6,%7}, {%8,%9}, {%0,%1,%2,%3};"
        : "+f"(d[0]), "+f"(d[1]), "+f"(d[2]), "+f"(d[3])
        : "r"(a[0]), "r"(a[1]), "r"(a[2]), "r"(a[3]), "r"(b[0]), "r"(b[1]));
}

// ---------------------------------------------------------------------------
// GEMM kernel — same verified swizzle/pipeline machinery as the int8 version;
// byte-level fragment addresses are IDENTICAL for m16n8k16.bf16:
//   A: a0=(row g, byte 4tg) a1=(row g+8, 4tg) a2/a3 = ^16; k-step = +32B.
//   B: b0=(n g, byte 4tg) b1 = ^16.
//   C: c0=(g,2tg) c1=(g,2tg+1) c2=(g+8,2tg) c3=(g+8,2tg+1)
// ---------------------------------------------------------------------------

__global__ void __launch_bounds__(NUM_THREADS, 1)
w8a8_hmma_kernel(float* __restrict__ out,
                 const float* __restrict__ bias,
                 const float* __restrict__ alpha_p)
{
    extern __shared__ char smem[];
    const uint32_t sb = smem_u32(smem);
    const int tid = threadIdx.x;
    const int wid = tid >> 5;
    const int lid = tid & 31;

    const int m_base = blockIdx.y * BM;
    const int n_base = blockIdx.x * BN;

    const int warp_m = wid & 1;    // 0..1 -> 64-row slab
    const int warp_n = wid >> 1;   // 0..3 -> 32-col slab

    // ---- producer precompute: 4 A + 4 B 16B units per thread --------------
    // store swizzle: (row r, 16B-col c) -> r*BKB + (c ^ ((r&7)<<4))   [bytes]
    uint32_t dst_off[4];
    const __nv_bfloat16* a_src[4];
    const __nv_bfloat16* b_src[4];
    #pragma unroll
    for (int i = 0; i < 4; i++) {
        const int u = tid + i * 256;           // 0..1023 units
        const int r = u >> 3;                  // tile row 0..127
        const int cb = (u & 7) * 16;           // byte col 0..112
        dst_off[i] = (uint32_t)(r * BKB + (cb ^ ((r & 7) << 4)));
        const int ce = cb / 2;                 // element col 0..56
        a_src[i] = g_xh + (size_t)(m_base + r) * K_TOTAL + ce;
        b_src[i] = g_wh + (size_t)(n_base + r) * K_TOTAL + ce;
    }

    // ---- consumer precompute ----------------------------------------------
    const int g  = lid >> 2;
    const int tg = lid & 3;
    const uint32_t maskg = (uint32_t)(g << 4);
    const uint32_t kbase = (uint32_t)(4 * tg);
    const uint32_t a_row_off = (uint32_t)((warp_m * 64 + g) * BKB);
    const uint32_t b_row_off = (uint32_t)((warp_n * 32 + g) * BKB);

    float acc[4][4][4];
    #pragma unroll
    for (int fm = 0; fm < 4; fm++)
        #pragma unroll
        for (int fn = 0; fn < 4; fn++)
            #pragma unroll
            for (int q = 0; q < 4; q++) acc[fm][fn][q] = 0.0f;

    // ---- prologue: fill stages 0..2 ---------------------------------------
    #pragma unroll
    for (int s = 0; s < STAGES - 1; s++) {
        const uint32_t sA = sb + s * STAGE_BYTES;
        const uint32_t sB = sA + A_BYTES;
        #pragma unroll
        for (int i = 0; i < 4; i++) cp16(sA + dst_off[i], a_src[i] + s * BK_ELEM);
        #pragma unroll
        for (int i = 0; i < 4; i++) cp16(sB + dst_off[i], b_src[i] + s * BK_ELEM);
        cp_commit();
    }

    // ---- main loop --------------------------------------------------------
    #pragma unroll 1
    for (int kc = 0; kc < K_CHUNKS; kc++) {
        cp_wait<STAGES - 2>();
        __syncthreads();

        const int kn = kc + STAGES - 1;
        if (kn < K_CHUNKS) {
            const int s = kn & (STAGES - 1);
            const uint32_t sA = sb + s * STAGE_BYTES;
            const uint32_t sB = sA + A_BYTES;
            #pragma unroll
            for (int i = 0; i < 4; i++) cp16(sA + dst_off[i], a_src[i] + kn * BK_ELEM);
            #pragma unroll
            for (int i = 0; i < 4; i++) cp16(sB + dst_off[i], b_src[i] + kn * BK_ELEM);
        }
        cp_commit();

        const char* sAp = smem + (kc & (STAGES - 1)) * STAGE_BYTES;
        const char* sBp = sAp + A_BYTES;

        #pragma unroll
        for (int ks = 0; ks < 4; ks++) {          // 4 x k16 per 128B chunk
            const uint32_t c0 = ((uint32_t)(ks << 5) + kbase) ^ maskg;
            const uint32_t c1 = c0 ^ 16u;

            uint32_t a[4][4];
            #pragma unroll
            for (int fm = 0; fm < 4; fm++) {
                const char* base = sAp + a_row_off + fm * (16 * BKB);
                a[fm][0] = *reinterpret_cast<const uint32_t*>(base + c0);
                a[fm][1] = *reinterpret_cast<const uint32_t*>(base + 8 * BKB + c0);
                a[fm][2] = *reinterpret_cast<const uint32_t*>(base + c1);
                a[fm][3] = *reinterpret_cast<const uint32_t*>(base + 8 * BKB + c1);
            }
            uint32_t bf[4][2];
            #pragma unroll
            for (int fn = 0; fn < 4; fn++) {
                const char* base = sBp + b_row_off + fn * (8 * BKB);
                bf[fn][0] = *reinterpret_cast<const uint32_t*>(base + c0);
                bf[fn][1] = *reinterpret_cast<const uint32_t*>(base + c1);
            }
            #pragma unroll
            for (int fm = 0; fm < 4; fm++)
                #pragma unroll
                for (int fn = 0; fn < 4; fn++)
                    hmma16816(acc[fm][fn], a[fm], bf[fn]);
        }
    }
    cp_wait<0>();

    // ---- epilogue: alpha * acc + bias -------------------------------------
    const float alpha = __ldg(alpha_p);

    #pragma unroll
    for (int fm = 0; fm < 4; fm++) {
        const int row = m_base + warp_m * 64 + fm * 16 + g;
        float* o0 = out + (size_t)row * N_TOTAL;
        float* o1 = out + (size_t)(row + 8) * N_TOTAL;
        #pragma unroll
        for (int fn = 0; fn < 4; fn++) {
            const int col = n_base + warp_n * 32 + fn * 8 + tg * 2;
            const float b0 = __ldg(bias + col);
            const float b1 = __ldg(bias + col + 1);
            float2 v0, v1;
            v0.x = fmaf(alpha, acc[fm][fn][0], b0);
            v0.y = fmaf(alpha, acc[fm][fn][1], b1);
            v1.x = fmaf(alpha, acc[fm][fn][2], b0);
            v1.y = fmaf(alpha, acc[fm][fn][3], b1);
            *reinterpret_cast<float2*>(o0 + col) = v0;
            *reinterpret_cast<float2*>(o1 + col) = v1;
        }
    }
}

// ---------------------------------------------------------------------------
// Launch — inputs identified by element count; M from out_size.
// ---------------------------------------------------------------------------

extern "C" void kernel_launch(void* const* d_in, const int* in_sizes, int n_in,
                              void* d_out, int out_size)
{
    const void* px = nullptr;
    const void* pw = nullptr;
    const void* pb = nullptr;
    const void* pa = nullptr;

    for (int i = 0; i < n_in; i++) {
        const long s = (long)in_sizes[i];
        if (s == 1)                            pa = d_in[i];
        else if (s == (long)N_TOTAL)           pb = d_in[i];
        else if (s == (long)N_TOTAL * K_TOTAL) pw = d_in[i];
        else                                   px = d_in[i];
    }
    if (!px || !pw || !pb || !pa) {   // fallback: declared order
        px = d_in[0]; pw = d_in[1]; pb = d_in[2]; pa = d_in[3];
    }

    const int M = out_size / N_TOTAL;            // 8192
    const int nx8 = (M * K_TOTAL) / 8;           // 4,194,304
    const int nw8 = (N_TOTAL * K_TOTAL) / 8;     // 2,097,152

    detect_kernel<<<1, 32>>>((const int*)px);
    cvt_bf16_kernel<<<(nx8 + 255) / 256, 256>>>(px, 0, nx8);
    cvt_bf16_kernel<<<(nw8 + 255) / 256, 256>>>(pw, 1, nw8);

    cudaFuncSetAttribute(w8a8_hmma_kernel,
                         cudaFuncAttributeMaxDynamicSharedMemorySize, SMEM_TOTAL);

    dim3 grid(N_TOTAL / BN, M / BM);   // (32, 64)
    w8a8_hmma_kernel<<<grid, NUM_THREADS, SMEM_TOTAL>>>(
        (float*)d_out, (const float*)pb, (const float*)pa);
}

// round 11
// speedup vs baseline: 2.9231x; 1.2852x over previous
#include <cuda_runtime.h>
#include <cuda_bf16.h>
#include <cstdint>
#include <cstddef>

// ---------------------------------------------------------------------------
// W8A8 Linear via legacy bf16 HMMA (mma.sync.m16n8k16.f32.bf16.bf16.f32).
//
// R10: tensor=56.5% @ 1 CTA/SM, issue-bound. This round: ldmatrix fragment
// loads (6 LDSM vs 24 LDS per k-step) + 3-stage pipeline (96KB smem) +
// __launch_bounds__(256,2) for 2 CTAs/SM (4 warps/SMSP latency hiding).
//
//   out[m,n] = alpha * sum_k x[m,k]*w[n,k] + bias[n]
//
// Inputs arrive widened to 4-byte elements (established R6->R8); cvt kernels
// detect the encoding and emit packed bf16 scratch. Math is exact (int8
// values exact in bf16, products exact in fp32 accum, sums << 2^24).
// ---------------------------------------------------------------------------

static constexpr int K_TOTAL = 4096;
static constexpr int N_TOTAL = 4096;
static constexpr int M_MAX   = 8192;
static constexpr int BM = 128;
static constexpr int BN = 128;
static constexpr int BK_ELEM = 64;                   // bf16 elems per chunk
static constexpr int BKB = 128;                      // bytes per row per chunk
static constexpr int STAGES = 3;
static constexpr int K_CHUNKS = K_TOTAL / BK_ELEM;   // 64

static constexpr int A_BYTES = BM * BKB;                   // 16384
static constexpr int B_BYTES = BN * BKB;                   // 16384
static constexpr int STAGE_BYTES = A_BYTES + B_BYTES;      // 32768
static constexpr int SMEM_TOTAL = STAGES * STAGE_BYTES;    // 98304

static constexpr int NUM_THREADS = 256;

// ---------------------------------------------------------------------------
// Scratch (static device globals — no allocation)
// ---------------------------------------------------------------------------
__device__ __nv_bfloat16 g_xh[(size_t)M_MAX * K_TOTAL];    // 64 MB
__device__ __nv_bfloat16 g_wh[(size_t)N_TOTAL * K_TOTAL];  // 32 MB
__device__ int g_wide;                                     // 1 = 4B elements

// ---------------------------------------------------------------------------
// Input conversion
// ---------------------------------------------------------------------------

__device__ __forceinline__ float fix_elem(int v) {
    if ((unsigned)(v + 127) <= 254u) return (float)v;      // int32 encoding
    return __int_as_float(v);                              // float32 encoding
}

__global__ void detect_kernel(const int* __restrict__ probe) {
    if (threadIdx.x == 0) {
        int good = 0;
        for (int i = 0; i < 1024; i++) {
            const int v = probe[i];
            const float f = __int_as_float(v);
            const bool small_int = (unsigned)(v + 127) <= 254u;
            const bool small_flt = (f >= -127.5f && f <= 127.5f);
            if (small_int || small_flt) good++;
        }
        g_wide = (good >= 512) ? 1 : 0;
    }
}

// Each thread emits 8 bf16 (16B). Wide: reads 8x4B. Narrow: reads 8x1B int8.
__global__ void cvt_bf16_kernel(const void* __restrict__ src, int sel, int n8) {
    const int i = blockIdx.x * blockDim.x + threadIdx.x;
    if (i >= n8) return;
    __nv_bfloat16* dst = sel ? g_wh : g_xh;
    float v[8];
    if (g_wide) {
        const int4* s = reinterpret_cast<const int4*>(src) + (size_t)i * 2;
        const int4 w0 = s[0];
        const int4 w1 = s[1];
        v[0] = fix_elem(w0.x); v[1] = fix_elem(w0.y);
        v[2] = fix_elem(w0.z); v[3] = fix_elem(w0.w);
        v[4] = fix_elem(w1.x); v[5] = fix_elem(w1.y);
        v[6] = fix_elem(w1.z); v[7] = fix_elem(w1.w);
    } else {
        const uint2 p = reinterpret_cast<const uint2*>(src)[i];
        #pragma unroll
        for (int j = 0; j < 4; j++)
            v[j] = (float)(int8_t)((p.x >> (8 * j)) & 0xFFu);
        #pragma unroll
        for (int j = 0; j < 4; j++)
            v[4 + j] = (float)(int8_t)((p.y >> (8 * j)) & 0xFFu);
    }
    uint4 o;
    uint16_t h[8];
    #pragma unroll
    for (int j = 0; j < 8; j++) {
        const __nv_bfloat16 b = __float2bfloat16_rn(v[j]);
        h[j] = *reinterpret_cast<const uint16_t*>(&b);
    }
    o.x = (uint32_t)h[0] | ((uint32_t)h[1] << 16);
    o.y = (uint32_t)h[2] | ((uint32_t)h[3] << 16);
    o.z = (uint32_t)h[4] | ((uint32_t)h[5] << 16);
    o.w = (uint32_t)h[6] | ((uint32_t)h[7] << 16);
    reinterpret_cast<uint4*>(dst)[i] = o;
}

// ---------------------------------------------------------------------------
// PTX helpers (baseline PTX only)
// ---------------------------------------------------------------------------

__device__ __forceinline__ uint32_t smem_u32(const void* p) {
    uint32_t a;
    asm("{ .reg .u64 t; cvta.to.shared.u64 t, %1; cvt.u32.u64 %0, t; }"
        : "=r"(a) : "l"(p));
    return a;
}

__device__ __forceinline__ void cp16(uint32_t dst_smem, const void* src_gmem) {
    asm volatile("cp.async.cg.shared.global [%0], [%1], 16;"
                 :: "r"(dst_smem), "l"(src_gmem));
}

__device__ __forceinline__ void cp_commit() {
    asm volatile("cp.async.commit_group;" ::: "memory");
}

template <int N>
__device__ __forceinline__ void cp_wait() {
    asm volatile("cp.async.wait_group %0;" :: "n"(N) : "memory");
}

__device__ __forceinline__ void ldsm_x4(uint32_t* r, uint32_t addr) {
    asm volatile("ldmatrix.sync.aligned.m8n8.x4.shared.b16 {%0,%1,%2,%3}, [%4];"
                 : "=r"(r[0]), "=r"(r[1]), "=r"(r[2]), "=r"(r[3]) : "r"(addr));
}

__device__ __forceinline__ void hmma16816(float* d, const uint32_t* a,
                                          const uint32_t* b) {
    asm volatile(
        "mma.sync.aligned.m16n8k16.row.col.f32.bf16.bf16.f32 "
        "{%0,%1,%2,%3}, {%4,%5,%6,%7}, {%8,%9}, {%0,%1,%2,%3};"
        : "+f"(d[0]), "+f"(d[1]), "+f"(d[2]), "+f"(d[3])
        : "r"(a[0]), "r"(a[1]), "r"(a[2]), "r"(a[3]), "r"(b[0]), "r"(b[1]));
}

// ---------------------------------------------------------------------------
// GEMM kernel.  SMEM swizzle: (row r, byte col cb) -> r*128 + (cb^((r&7)<<4)).
//
// ldmatrix lane->address maps (m16n8k16 bf16 fragments):
//   A (x4, per fm 16-row block): matrices {rows 0-7 @k, rows 8-15 @k,
//     rows 0-7 @k+16B, rows 8-15 @k+16B} -> regs a0..a3.
//     lane l: row_in16 = l&15, k16 offset = l&16.
//   B (x4, per fn pair p): matrices {n 0-7 @k, n 0-7 @k+16B,
//     n 8-15 @k, n 8-15 @k+16B} -> regs {fn=2p b0,b1, fn=2p+1 b0,b1}.
//     lane l: row_in16 = (l&7) + ((l&16)>>1), k16 offset = (l&8)<<1.
// ---------------------------------------------------------------------------

__global__ void __launch_bounds__(NUM_THREADS, 2)
w8a8_hmma_kernel(float* __restrict__ out,
                 const float* __restrict__ bias,
                 const float* __restrict__ alpha_p)
{
    extern __shared__ char smem[];
    const uint32_t sb = smem_u32(smem);
    const int tid = threadIdx.x;
    const int wid = tid >> 5;
    const int lid = tid & 31;

    const int m_base = blockIdx.y * BM;
    const int n_base = blockIdx.x * BN;

    const int warp_m = wid & 1;    // 0..1 -> 64-row slab
    const int warp_n = wid >> 1;   // 0..3 -> 32-col slab

    // ---- producer precompute: 4 A + 4 B 16B units per thread --------------
    uint32_t dst_off[4];
    const __nv_bfloat16* a_src[4];
    const __nv_bfloat16* b_src[4];
    #pragma unroll
    for (int i = 0; i < 4; i++) {
        const int u = tid + i * 256;           // 0..1023 units
        const int r = u >> 3;                  // tile row 0..127
        const int cb = (u & 7) * 16;           // byte col 0..112
        dst_off[i] = (uint32_t)(r * BKB + (cb ^ ((r & 7) << 4)));
        const int ce = cb / 2;                 // element col
        a_src[i] = g_xh + (size_t)(m_base + r) * K_TOTAL + ce;
        b_src[i] = g_wh + (size_t)(n_base + r) * K_TOTAL + ce;
    }

    // ---- ldmatrix lane address precompute ---------------------------------
    const uint32_t lmask = (uint32_t)((lid & 7) << 4);              // swizzle
    const uint32_t a_k16 = (uint32_t)(lid & 16);                    // A koff
    const uint32_t b_k16 = (uint32_t)((lid & 8) << 1);              // B koff
    const uint32_t a_row16 = (uint32_t)(lid & 15);
    const uint32_t b_row16 = (uint32_t)((lid & 7) + ((lid & 16) >> 1));
    // per-lane row base (bytes into tile)
    const uint32_t a_rb = (uint32_t)((warp_m * 64 + a_row16) * BKB);
    const uint32_t b_rb = (uint32_t)((warp_n * 32 + b_row16) * BKB);

    float acc[4][4][4];
    #pragma unroll
    for (int fm = 0; fm < 4; fm++)
        #pragma unroll
        for (int fn = 0; fn < 4; fn++)
            #pragma unroll
            for (int q = 0; q < 4; q++) acc[fm][fn][q] = 0.0f;

    // ---- prologue: fill stages 0..1 ---------------------------------------
    #pragma unroll
    for (int s = 0; s < STAGES - 1; s++) {
        const uint32_t sA = sb + s * STAGE_BYTES;
        const uint32_t sB = sA + A_BYTES;
        #pragma unroll
        for (int i = 0; i < 4; i++) cp16(sA + dst_off[i], a_src[i] + s * BK_ELEM);
        #pragma unroll
        for (int i = 0; i < 4; i++) cp16(sB + dst_off[i], b_src[i] + s * BK_ELEM);
        cp_commit();
    }

    // ---- main loop --------------------------------------------------------
    int stage = 0;
    #pragma unroll 1
    for (int kc = 0; kc < K_CHUNKS; kc++) {
        cp_wait<STAGES - 2>();
        __syncthreads();

        const int kn = kc + STAGES - 1;
        if (kn < K_CHUNKS) {
            int sn = stage + STAGES - 1;
            if (sn >= STAGES) sn -= STAGES;
            const uint32_t sA = sb + sn * STAGE_BYTES;
            const uint32_t sB = sA + A_BYTES;
            #pragma unroll
            for (int i = 0; i < 4; i++) cp16(sA + dst_off[i], a_src[i] + kn * BK_ELEM);
            #pragma unroll
            for (int i = 0; i < 4; i++) cp16(sB + dst_off[i], b_src[i] + kn * BK_ELEM);
        }
        cp_commit();

        const uint32_t sA = sb + stage * STAGE_BYTES;
        const uint32_t sB = sA + A_BYTES;
        if (++stage == STAGES) stage = 0;

        #pragma unroll
        for (int ks = 0; ks < 4; ks++) {          // 4 x k16 per 128B chunk
            const uint32_t kb = (uint32_t)(ks << 5);
            const uint32_t aoff = (kb | a_k16) ^ lmask;
            const uint32_t boff = (kb | b_k16) ^ lmask;

            uint32_t a[4][4];
            #pragma unroll
            for (int fm = 0; fm < 4; fm++)
                ldsm_x4(a[fm], sA + a_rb + (uint32_t)(fm * 16 * BKB) + aoff);

            uint32_t bf[2][4];   // bf[p] = {fn=2p:b0,b1, fn=2p+1:b0,b1}
            #pragma unroll
            for (int p = 0; p < 2; p++)
                ldsm_x4(bf[p], sB + b_rb + (uint32_t)(p * 16 * BKB) + boff);

            #pragma unroll
            for (int fm = 0; fm < 4; fm++)
                #pragma unroll
                for (int fn = 0; fn < 4; fn++)
                    hmma16816(acc[fm][fn], a[fm], &bf[fn >> 1][(fn & 1) * 2]);
        }
    }
    cp_wait<0>();

    // ---- epilogue: alpha * acc + bias -------------------------------------
    const float alpha = __ldg(alpha_p);
    const int g  = lid >> 2;
    const int tg = lid & 3;

    #pragma unroll
    for (int fm = 0; fm < 4; fm++) {
        const int row = m_base + warp_m * 64 + fm * 16 + g;
        float* o0 = out + (size_t)row * N_TOTAL;
        float* o1 = out + (size_t)(row + 8) * N_TOTAL;
        #pragma unroll
        for (int fn = 0; fn < 4; fn++) {
            const int col = n_base + warp_n * 32 + fn * 8 + tg * 2;
            const float b0 = __ldg(bias + col);
            const float b1 = __ldg(bias + col + 1);
            float2 v0, v1;
            v0.x = fmaf(alpha, acc[fm][fn][0], b0);
            v0.y = fmaf(alpha, acc[fm][fn][1], b1);
            v1.x = fmaf(alpha, acc[fm][fn][2], b0);
            v1.y = fmaf(alpha, acc[fm][fn][3], b1);
            *reinterpret_cast<float2*>(o0 + col) = v0;
            *reinterpret_cast<float2*>(o1 + col) = v1;
        }
    }
}

// ---------------------------------------------------------------------------
// Launch — inputs identified by element count; M from out_size.
// ---------------------------------------------------------------------------

extern "C" void kernel_launch(void* const* d_in, const int* in_sizes, int n_in,
                              void* d_out, int out_size)
{
    const void* px = nullptr;
    const void* pw = nullptr;
    const void* pb = nullptr;
    const void* pa = nullptr;

    for (int i = 0; i < n_in; i++) {
        const long s = (long)in_sizes[i];
        if (s == 1)                            pa = d_in[i];
        else if (s == (long)N_TOTAL)           pb = d_in[i];
        else if (s == (long)N_TOTAL * K_TOTAL) pw = d_in[i];
        else                                   px = d_in[i];
    }
    if (!px || !pw || !pb || !pa) {   // fallback: declared order
        px = d_in[0]; pw = d_in[1]; pb = d_in[2]; pa = d_in[3];
    }

    const int M = out_size / N_TOTAL;            // 8192
    const int nx8 = (M * K_TOTAL) / 8;
    const int nw8 = (N_TOTAL * K_TOTAL) / 8;

    detect_kernel<<<1, 32>>>((const int*)px);
    cvt_bf16_kernel<<<(nx8 + 255) / 256, 256>>>(px, 0, nx8);
    cvt_bf16_kernel<<<(nw8 + 255) / 256, 256>>>(pw, 1, nw8);

    cudaFuncSetAttribute(w8a8_hmma_kernel,
                         cudaFuncAttributeMaxDynamicSharedMemorySize, SMEM_TOTAL);

    dim3 grid(N_TOTAL / BN, M / BM);   // (32, 64)
    w8a8_hmma_kernel<<<grid, NUM_THREADS, SMEM_TOTAL>>>(
        (float*)d_out, (const float*)pb, (const float*)pa);
}

// round 12
// speedup vs baseline: 2.9793x; 1.0193x over previous
#include <cuda_runtime.h>
#include <cuda_bf16.h>
#include <cstdint>
#include <cstddef>

// ---------------------------------------------------------------------------
// W8A8 Linear via legacy bf16 HMMA (mma.sync.m16n8k16.f32.bf16.bf16.f32).
//
// R11: tensor=75.2%, GEMM 600us @ 2 CTA/SM, regs=128 (RF fully subscribed).
// Remaining bubble attributed to MIO contention: the 8-deep cp.async burst at
// each chunk head delays that chunk's ldmatrix stream (LDGSTS and LDSM share
// the LSU/MIO path). Fix: interleave 2 cp16 per k-step AFTER the LDSMs, so
// prefetch rides in the HMMA shadow. Commit moves to the last k-step.
//
//   out[m,n] = alpha * sum_k x[m,k]*w[n,k] + bias[n]
//
// Inputs arrive widened to 4-byte elements (established R6->R8); cvt kernels
// detect the encoding and emit packed bf16 scratch. Math exact.
// ---------------------------------------------------------------------------

static constexpr int K_TOTAL = 4096;
static constexpr int N_TOTAL = 4096;
static constexpr int M_MAX   = 8192;
static constexpr int BM = 128;
static constexpr int BN = 128;
static constexpr int BK_ELEM = 64;                   // bf16 elems per chunk
static constexpr int BKB = 128;                      // bytes per row per chunk
static constexpr int STAGES = 3;
static constexpr int K_CHUNKS = K_TOTAL / BK_ELEM;   // 64

static constexpr int A_BYTES = BM * BKB;                   // 16384
static constexpr int B_BYTES = BN * BKB;                   // 16384
static constexpr int STAGE_BYTES = A_BYTES + B_BYTES;      // 32768
static constexpr int SMEM_TOTAL = STAGES * STAGE_BYTES;    // 98304

static constexpr int NUM_THREADS = 256;

// ---------------------------------------------------------------------------
// Scratch (static device globals — no allocation)
// ---------------------------------------------------------------------------
__device__ __nv_bfloat16 g_xh[(size_t)M_MAX * K_TOTAL];    // 64 MB
__device__ __nv_bfloat16 g_wh[(size_t)N_TOTAL * K_TOTAL];  // 32 MB
__device__ int g_wide;                                     // 1 = 4B elements

// ---------------------------------------------------------------------------
// Input conversion
// ---------------------------------------------------------------------------

__device__ __forceinline__ float fix_elem(int v) {
    if ((unsigned)(v + 127) <= 254u) return (float)v;      // int32 encoding
    return __int_as_float(v);                              // float32 encoding
}

__global__ void detect_kernel(const int* __restrict__ probe) {
    // warp-cooperative: 32 lanes x 32 probes
    const int lid = threadIdx.x & 31;
    int good = 0;
    for (int i = lid; i < 1024; i += 32) {
        const int v = probe[i];
        const float f = __int_as_float(v);
        const bool small_int = (unsigned)(v + 127) <= 254u;
        const bool small_flt = (f >= -127.5f && f <= 127.5f);
        if (small_int || small_flt) good++;
    }
    #pragma unroll
    for (int s = 16; s > 0; s >>= 1)
        good += __shfl_xor_sync(0xFFFFFFFFu, good, s);
    if (lid == 0) g_wide = (good >= 512) ? 1 : 0;
}

// Each thread emits 8 bf16 (16B). Wide: reads 8x4B. Narrow: reads 8x1B int8.
__global__ void cvt_bf16_kernel(const void* __restrict__ src, int sel, int n8) {
    const int i = blockIdx.x * blockDim.x + threadIdx.x;
    if (i >= n8) return;
    __nv_bfloat16* dst = sel ? g_wh : g_xh;
    float v[8];
    if (g_wide) {
        const int4* s = reinterpret_cast<const int4*>(src) + (size_t)i * 2;
        const int4 w0 = s[0];
        const int4 w1 = s[1];
        v[0] = fix_elem(w0.x); v[1] = fix_elem(w0.y);
        v[2] = fix_elem(w0.z); v[3] = fix_elem(w0.w);
        v[4] = fix_elem(w1.x); v[5] = fix_elem(w1.y);
        v[6] = fix_elem(w1.z); v[7] = fix_elem(w1.w);
    } else {
        const uint2 p = reinterpret_cast<const uint2*>(src)[i];
        #pragma unroll
        for (int j = 0; j < 4; j++)
            v[j] = (float)(int8_t)((p.x >> (8 * j)) & 0xFFu);
        #pragma unroll
        for (int j = 0; j < 4; j++)
            v[4 + j] = (float)(int8_t)((p.y >> (8 * j)) & 0xFFu);
    }
    uint4 o;
    uint16_t h[8];
    #pragma unroll
    for (int j = 0; j < 8; j++) {
        const __nv_bfloat16 b = __float2bfloat16_rn(v[j]);
        h[j] = *reinterpret_cast<const uint16_t*>(&b);
    }
    o.x = (uint32_t)h[0] | ((uint32_t)h[1] << 16);
    o.y = (uint32_t)h[2] | ((uint32_t)h[3] << 16);
    o.z = (uint32_t)h[4] | ((uint32_t)h[5] << 16);
    o.w = (uint32_t)h[6] | ((uint32_t)h[7] << 16);
    reinterpret_cast<uint4*>(dst)[i] = o;
}

// ---------------------------------------------------------------------------
// PTX helpers (baseline PTX only)
// ---------------------------------------------------------------------------

__device__ __forceinline__ uint32_t smem_u32(const void* p) {
    uint32_t a;
    asm("{ .reg .u64 t; cvta.to.shared.u64 t, %1; cvt.u32.u64 %0, t; }"
        : "=r"(a) : "l"(p));
    return a;
}

__device__ __forceinline__ void cp16(uint32_t dst_smem, const void* src_gmem) {
    asm volatile("cp.async.cg.shared.global [%0], [%1], 16;"
                 :: "r"(dst_smem), "l"(src_gmem));
}

__device__ __forceinline__ void cp_commit() {
    asm volatile("cp.async.commit_group;" ::: "memory");
}

template <int N>
__device__ __forceinline__ void cp_wait() {
    asm volatile("cp.async.wait_group %0;" :: "n"(N) : "memory");
}

__device__ __forceinline__ void ldsm_x4(uint32_t* r, uint32_t addr) {
    asm volatile("ldmatrix.sync.aligned.m8n8.x4.shared.b16 {%0,%1,%2,%3}, [%4];"
                 : "=r"(r[0]), "=r"(r[1]), "=r"(r[2]), "=r"(r[3]) : "r"(addr));
}

__device__ __forceinline__ void hmma16816(float* d, const uint32_t* a,
                                          const uint32_t* b) {
    asm volatile(
        "mma.sync.aligned.m16n8k16.row.col.f32.bf16.bf16.f32 "
        "{%0,%1,%2,%3}, {%4,%5,%6,%7}, {%8,%9}, {%0,%1,%2,%3};"
        : "+f"(d[0]), "+f"(d[1]), "+f"(d[2]), "+f"(d[3])
        : "r"(a[0]), "r"(a[1]), "r"(a[2]), "r"(a[3]), "r"(b[0]), "r"(b[1]));
}

// ---------------------------------------------------------------------------
// GEMM kernel.  SMEM swizzle: (row r, byte col cb) -> r*128 + (cb^((r&7)<<4)).
// ldmatrix lane->address maps as verified in R11 (bit-exact result).
// ---------------------------------------------------------------------------

__global__ void __launch_bounds__(NUM_THREADS, 2)
w8a8_hmma_kernel(float* __restrict__ out,
                 const float* __restrict__ bias,
                 const float* __restrict__ alpha_p)
{
    extern __shared__ char smem[];
    const uint32_t sb = smem_u32(smem);
    const int tid = threadIdx.x;
    const int wid = tid >> 5;
    const int lid = tid & 31;

    const int m_base = blockIdx.y * BM;
    const int n_base = blockIdx.x * BN;

    const int warp_m = wid & 1;    // 0..1 -> 64-row slab
    const int warp_n = wid >> 1;   // 0..3 -> 32-col slab

    // ---- producer precompute: 4 A + 4 B 16B units per thread --------------
    uint32_t dst_off[4];
    const __nv_bfloat16* a_src[4];
    const __nv_bfloat16* b_src[4];
    #pragma unroll
    for (int i = 0; i < 4; i++) {
        const int u = tid + i * 256;           // 0..1023 units
        const int r = u >> 3;                  // tile row 0..127
        const int cb = (u & 7) * 16;           // byte col 0..112
        dst_off[i] = (uint32_t)(r * BKB + (cb ^ ((r & 7) << 4)));
        const int ce = cb / 2;                 // element col
        a_src[i] = g_xh + (size_t)(m_base + r) * K_TOTAL + ce;
        b_src[i] = g_wh + (size_t)(n_base + r) * K_TOTAL + ce;
    }

    // ---- ldmatrix lane address precompute ---------------------------------
    const uint32_t lmask = (uint32_t)((lid & 7) << 4);              // swizzle
    const uint32_t a_k16 = (uint32_t)(lid & 16);                    // A koff
    const uint32_t b_k16 = (uint32_t)((lid & 8) << 1);              // B koff
    const uint32_t a_row16 = (uint32_t)(lid & 15);
    const uint32_t b_row16 = (uint32_t)((lid & 7) + ((lid & 16) >> 1));
    const uint32_t a_rb = (uint32_t)((warp_m * 64 + a_row16) * BKB);
    const uint32_t b_rb = (uint32_t)((warp_n * 32 + b_row16) * BKB);

    float acc[4][4][4];
    #pragma unroll
    for (int fm = 0; fm < 4; fm++)
        #pragma unroll
        for (int fn = 0; fn < 4; fn++)
            #pragma unroll
            for (int q = 0; q < 4; q++) acc[fm][fn][q] = 0.0f;

    // ---- prologue: fill stages 0..1 ---------------------------------------
    #pragma unroll
    for (int s = 0; s < STAGES - 1; s++) {
        const uint32_t sA = sb + s * STAGE_BYTES;
        const uint32_t sB = sA + A_BYTES;
        #pragma unroll
        for (int i = 0; i < 4; i++) cp16(sA + dst_off[i], a_src[i] + s * BK_ELEM);
        #pragma unroll
        for (int i = 0; i < 4; i++) cp16(sB + dst_off[i], b_src[i] + s * BK_ELEM);
        cp_commit();
    }

    // ---- main loop --------------------------------------------------------
    int stage = 0;
    #pragma unroll 1
    for (int kc = 0; kc < K_CHUNKS; kc++) {
        cp_wait<STAGES - 2>();
        __syncthreads();

        const int kn = kc + STAGES - 1;
        const bool pref = (kn < K_CHUNKS);
        int sn = stage + STAGES - 1;
        if (sn >= STAGES) sn -= STAGES;
        const uint32_t pA = sb + sn * STAGE_BYTES;
        const uint32_t pB = pA + A_BYTES;
        const int koff = kn * BK_ELEM;

        const uint32_t sA = sb + stage * STAGE_BYTES;
        const uint32_t sB = sA + A_BYTES;
        if (++stage == STAGES) stage = 0;

        // 4 x k16 steps; 2 cp16 prefetches interleaved per step AFTER the
        // step's LDSMs so LDGSTS bursts ride in the HMMA shadow (MIO share).
        #pragma unroll
        for (int ks = 0; ks < 4; ks++) {
            const uint32_t kb = (uint32_t)(ks << 5);
            const uint32_t aoff = (kb | a_k16) ^ lmask;
            const uint32_t boff = (kb | b_k16) ^ lmask;

            uint32_t a[4][4];
            #pragma unroll
            for (int fm = 0; fm < 4; fm++)
                ldsm_x4(a[fm], sA + a_rb + (uint32_t)(fm * 16 * BKB) + aoff);

            uint32_t bf[2][4];   // bf[p] = {fn=2p:b0,b1, fn=2p+1:b0,b1}
            #pragma unroll
            for (int p = 0; p < 2; p++)
                ldsm_x4(bf[p], sB + b_rb + (uint32_t)(p * 16 * BKB) + boff);

            if (pref) {
                if (ks < 2) {    // A units: ks=0 -> 0,1 ; ks=1 -> 2,3
                    cp16(pA + dst_off[2 * ks],     a_src[2 * ks] + koff);
                    cp16(pA + dst_off[2 * ks + 1], a_src[2 * ks + 1] + koff);
                } else {         // B units: ks=2 -> 0,1 ; ks=3 -> 2,3
                    cp16(pB + dst_off[2 * (ks - 2)],     b_src[2 * (ks - 2)] + koff);
                    cp16(pB + dst_off[2 * (ks - 2) + 1], b_src[2 * (ks - 2) + 1] + koff);
                }
            }
            if (ks == 3) cp_commit();   // exactly one group per iteration

            #pragma unroll
            for (int fm = 0; fm < 4; fm++)
                #pragma unroll
                for (int fn = 0; fn < 4; fn++)
                    hmma16816(acc[fm][fn], a[fm], &bf[fn >> 1][(fn & 1) * 2]);
        }
    }
    cp_wait<0>();

    // ---- epilogue: alpha * acc + bias -------------------------------------
    const float alpha = __ldg(alpha_p);
    const int g  = lid >> 2;
    const int tg = lid & 3;

    #pragma unroll
    for (int fm = 0; fm < 4; fm++) {
        const int row = m_base + warp_m * 64 + fm * 16 + g;
        float* o0 = out + (size_t)row * N_TOTAL;
        float* o1 = out + (size_t)(row + 8) * N_TOTAL;
        #pragma unroll
        for (int fn = 0; fn < 4; fn++) {
            const int col = n_base + warp_n * 32 + fn * 8 + tg * 2;
            const float b0 = __ldg(bias + col);
            const float b1 = __ldg(bias + col + 1);
            float2 v0, v1;
            v0.x = fmaf(alpha, acc[fm][fn][0], b0);
            v0.y = fmaf(alpha, acc[fm][fn][1], b1);
            v1.x = fmaf(alpha, acc[fm][fn][2], b0);
            v1.y = fmaf(alpha, acc[fm][fn][3], b1);
            *reinterpret_cast<float2*>(o0 + col) = v0;
            *reinterpret_cast<float2*>(o1 + col) = v1;
        }
    }
}

// ---------------------------------------------------------------------------
// Launch — inputs identified by element count; M from out_size.
// ---------------------------------------------------------------------------

extern "C" void kernel_launch(void* const* d_in, const int* in_sizes, int n_in,
                              void* d_out, int out_size)
{
    const void* px = nullptr;
    const void* pw = nullptr;
    const void* pb = nullptr;
    const void* pa = nullptr;

    for (int i = 0; i < n_in; i++) {
        const long s = (long)in_sizes[i];
        if (s == 1)                            pa = d_in[i];
        else if (s == (long)N_TOTAL)           pb = d_in[i];
        else if (s == (long)N_TOTAL * K_TOTAL) pw = d_in[i];
        else                                   px = d_in[i];
    }
    if (!px || !pw || !pb || !pa) {   // fallback: declared order
        px = d_in[0]; pw = d_in[1]; pb = d_in[2]; pa = d_in[3];
    }

    const int M = out_size / N_TOTAL;            // 8192
    const int nx8 = (M * K_TOTAL) / 8;
    const int nw8 = (N_TOTAL * K_TOTAL) / 8;

    detect_kernel<<<1, 32>>>((const int*)px);
    cvt_bf16_kernel<<<(nx8 + 255) / 256, 256>>>(px, 0, nx8);
    cvt_bf16_kernel<<<(nw8 + 255) / 256, 256>>>(pw, 1, nw8);

    cudaFuncSetAttribute(w8a8_hmma_kernel,
                         cudaFuncAttributeMaxDynamicSharedMemorySize, SMEM_TOTAL);

    dim3 grid(N_TOTAL / BN, M / BM);   // (32, 64)
    w8a8_hmma_kernel<<<grid, NUM_THREADS, SMEM_TOTAL>>>(
        (float*)d_out, (const float*)pb, (const float*)pa);
}